// round 7
// baseline (speedup 1.0000x reference)
#include <cuda_runtime.h>

#define NPATHS 100000
#define NLINKS 10000

// ---------------- persistent device state ----------------
__device__ __align__(16) float g_link_state[NLINKS * 32];
__device__ __align__(16) float g_path_state[NPATHS * 32];
__device__ __align__(16) float g_m[NLINKS * 32];          // segment sums
__device__ __align__(16) float g_LG[NLINKS * 96];         // link_state @ Wp + biases

// ---------------- packed f32x2 helpers ----------------
typedef unsigned long long u64;

__device__ __forceinline__ u64 splat2(float x) {
    u64 r; asm("mov.b64 %0, {%1, %1};" : "=l"(r) : "f"(x)); return r;
}
__device__ __forceinline__ u64 pack2(float a, float b) {
    u64 r; asm("mov.b64 %0, {%1, %2};" : "=l"(r) : "f"(a), "f"(b)); return r;
}
__device__ __forceinline__ void unpack2(u64 v, float& a, float& b) {
    asm("mov.b64 {%0, %1}, %2;" : "=f"(a), "=f"(b) : "l"(v));
}
__device__ __forceinline__ void ffma2(u64& d, u64 a, u64 b) {
    asm("fma.rn.f32x2 %0, %1, %2, %0;" : "+l"(d) : "l"(a), "l"(b));
}
__device__ __forceinline__ u64 lds_b64(unsigned addr) {
    u64 r; asm volatile("ld.shared.b64 %0, [%1];" : "=l"(r) : "r"(addr)); return r;
}
__device__ __forceinline__ void ldg_v2(const void* p, u64& a, u64& b) {
    asm volatile("ld.global.nc.v2.u64 {%0, %1}, [%2];" : "=l"(a), "=l"(b) : "l"(p));
}

// ---------------- fast activations ----------------
__device__ __forceinline__ float sigmoidf_(float x) {
    return __fdividef(1.0f, 1.0f + __expf(-x));
}
__device__ __forceinline__ float tanhfast_(float x) {
    float e = __expf(2.0f * x);
    return 1.0f - __fdividef(2.0f, e + 1.0f);
}
__device__ __forceinline__ float seluf_(float x) {
    const float sc = 1.0507009873554805f;
    const float al = 1.6732632423543772f;
    return x > 0.0f ? sc * x : sc * al * (__expf(x) - 1.0f);
}

// ---------------- init: states, m=0, initial LG ----------------
__global__ void k_init(const float* __restrict__ cap, const float* __restrict__ traffic,
                       const float* __restrict__ Wp, const float* __restrict__ bp) {
    int idx = blockIdx.x * blockDim.x + threadIdx.x;
    if (idx < NPATHS * 32)
        g_path_state[idx] = ((idx & 31) == 0) ? traffic[idx >> 5] : 0.0f;
    if (idx < NLINKS * 32) {
        g_link_state[idx] = ((idx & 31) == 0) ? cap[idx >> 5] : 0.0f;
        g_m[idx] = 0.0f;
    }
    if (idx < NLINKS * 96) {
        int l = idx / 96;
        int j = idx - l * 96;
        float v = cap[l] * Wp[j] + bp[j];        // input bias bp[0]
        if (j < 64) v += bp[96 + j];             // fold recurrent bias bp[1] for z,r
        g_LG[idx] = v;
    }
}

// ---------------- path phase v4: lane=dim, warp=16 paths, load-early/add-late
#define PPW 16          // paths per warp
#define NPAIR 8         // path pairs per warp
#define HSTR 9          // u64 stride per dim row (8 pairs + 1 pad)

__global__ void __launch_bounds__(128)
k_path(const int* __restrict__ links, const float* __restrict__ Up,
       const float* __restrict__ bp) {
    __shared__ __align__(16) float sUp[3072];          // Up [k][j] row-major
    __shared__ int slinks[64 * 8];                     // 64 paths per block
    __shared__ __align__(16) u64 sh2[4 * 32 * HSTR];   // per warp: h[dim][pair]

    const int tid  = threadIdx.x;
    const int lane = tid & 31;
    const int warp = tid >> 5;
    const int p0   = blockIdx.x * 64;                  // 64 paths per block

    for (int i = tid; i < 3072; i += 128) sUp[i] = Up[i];
    for (int i = tid; i < 512; i += 128) {
        int e = p0 * 8 + i;
        slinks[i] = (e < NPATHS * 8) ? links[e] : 0;
    }
    __syncthreads();

    const int pw = p0 + warp * PPW;
    if (pw >= NPATHS) return;                          // whole-warp exit

    u64* shw = sh2 + warp * 32 * HSTR;
    float* shf = reinterpret_cast<float*>(shw);

    // load h tile: float idx = dim*2*HSTR + pathInWarp
    #pragma unroll 1
    for (int i = 0; i < PPW; i++)
        shf[lane * 2 * HSTR + i] = g_path_state[(pw + i) * 32 + lane];
    __syncwarp();

    const u64 b1h2 = splat2(__ldg(bp + 96 + 64 + lane));
    const unsigned shw_a = (unsigned)__cvta_generic_to_shared(shw);
    const int* slk = slinks + warp * PPW * 8;

    #pragma unroll 1
    for (int s = 0; s < 8; s++) {
        // prologue: issue ALL LG gather loads now; consumed only after k-loop
        float pz[PPW], pr[PPW], ph[PPW];
        #pragma unroll
        for (int q = 0; q < PPW; q++) {
            const float* lg = g_LG + slk[q * 8 + s] * 96 + lane;
            pz[q] = __ldg(lg);
            pr[q] = __ldg(lg + 32);
            ph[q] = __ldg(lg + 64);
        }

        u64 accz[NPAIR], accr[NPAIR], acch[NPAIR];
        #pragma unroll
        for (int p2 = 0; p2 < NPAIR; p2++) {
            accz[p2] = 0ull;
            accr[p2] = 0ull;
            acch[p2] = b1h2;
        }

        // recurrent matvec: acc += h @ Up (gather latency hidden underneath)
        #pragma unroll 2
        for (int k = 0; k < 32; k++) {
            const float* w = sUp + k * 96 + lane;
            u64 wz2 = splat2(w[0]);
            u64 wr2 = splat2(w[32]);
            u64 wh2 = splat2(w[64]);
            unsigned ha = shw_a + (unsigned)(k * HSTR * 8);
            #pragma unroll
            for (int p2 = 0; p2 < NPAIR; p2++) {
                u64 h2 = lds_b64(ha + p2 * 8);
                ffma2(accz[p2], h2, wz2);
                ffma2(accr[p2], h2, wr2);
                ffma2(acch[p2], h2, wh2);
            }
        }

        // epilogue: add prefetched LG, gates, state update, coalesced scatter
        #pragma unroll
        for (int p2 = 0; p2 < NPAIR; p2++) {
            int qA = 2 * p2, qB = qA + 1;
            int lkA = slk[qA * 8 + s];
            int lkB = slk[qB * 8 + s];
            float azA, azB, arA, arB, ahA, ahB;
            unpack2(accz[p2], azA, azB);
            unpack2(accr[p2], arA, arB);
            unpack2(acch[p2], ahA, ahB);
            float* hp = shf + lane * 2 * HSTR + 2 * p2;

            float zA = sigmoidf_(azA + pz[qA]);
            float rA = sigmoidf_(arA + pr[qA]);
            float cA = tanhfast_(ph[qA] + rA * ahA);
            float hoA = hp[0];
            float hnA = cA + zA * (hoA - cA);
            hp[0] = hnA;
            atomicAdd(g_m + lkA * 32 + lane, hnA);

            float zB = sigmoidf_(azB + pz[qB]);
            float rB = sigmoidf_(arB + pr[qB]);
            float cB = tanhfast_(ph[qB] + rB * ahB);
            float hoB = hp[1];
            float hnB = cB + zB * (hoB - cB);
            hp[1] = hnB;
            atomicAdd(g_m + lkB * 32 + lane, hnB);
        }
        __syncwarp();
    }

    // writeback h tile (coalesced per path)
    #pragma unroll 1
    for (int i = 0; i < PPW; i++)
        g_path_state[(pw + i) * 32 + lane] = shf[lane * 2 * HSTR + i];
}

// ---------------- link phase v3: warp per link, looped (amortize weights) ---
#define LINK_WARPS 512        // 64 blocks * 8 warps

__global__ void __launch_bounds__(256)
k_link(const float* __restrict__ Wl, const float* __restrict__ Ul,
       const float* __restrict__ bl, const float* __restrict__ Wp,
       const float* __restrict__ bp) {
    __shared__ float sWl[3072], sUl[3072], sWp[3072];
    __shared__ float sbl[192], sbp[192];
    const int tid = threadIdx.x;
    for (int i = tid; i < 3072; i += 256) { sWl[i] = Wl[i]; sUl[i] = Ul[i]; sWp[i] = Wp[i]; }
    if (tid < 192) { sbl[tid] = bl[tid]; sbp[tid] = bp[tid]; }
    __syncthreads();

    const int lane = tid & 31;
    const int gw = blockIdx.x * 8 + (tid >> 5);       // global warp id, 0..511

    const float az0  = sbl[lane]      + sbl[96 + lane];
    const float ar0  = sbl[32 + lane] + sbl[128 + lane];
    const float axh0 = sbl[64 + lane];
    const float ahh0 = sbl[160 + lane];
    const float lg0  = sbp[lane]      + sbp[96 + lane];
    const float lg1  = sbp[32 + lane] + sbp[128 + lane];
    const float lg2  = sbp[64 + lane];

    #pragma unroll 1
    for (int L = gw; L < NLINKS; L += LINK_WARPS) {
        float mown = g_m[L * 32 + lane];
        float hown = g_link_state[L * 32 + lane];

        float az = az0, arx = ar0, axh = axh0, ahh = ahh0;

        #pragma unroll 1
        for (int k = 0; k < 32; k++) {
            float mk = __shfl_sync(0xffffffffu, mown, k);
            float hk = __shfl_sync(0xffffffffu, hown, k);
            const float* wl = sWl + k * 96 + lane;
            const float* ul = sUl + k * 96 + lane;
            az  = fmaf(mk, wl[0],  fmaf(hk, ul[0],  az));
            arx = fmaf(mk, wl[32], fmaf(hk, ul[32], arx));
            axh = fmaf(mk, wl[64], axh);
            ahh = fmaf(hk, ul[64], ahh);
        }

        float z  = sigmoidf_(az);
        float r  = sigmoidf_(arx);
        float c  = tanhfast_(axh + r * ahh);
        float hn = c + z * (hown - c);

        g_link_state[L * 32 + lane] = hn;
        g_m[L * 32 + lane] = 0.0f;                    // reset for next iteration

        // recompute LG = new_link_state @ Wp + biases
        float l0 = lg0, l1 = lg1, l2 = lg2;
        #pragma unroll 1
        for (int k = 0; k < 32; k++) {
            float hk = __shfl_sync(0xffffffffu, hn, k);
            const float* wp = sWp + k * 96 + lane;
            l0 = fmaf(hk, wp[0],  l0);
            l1 = fmaf(hk, wp[32], l1);
            l2 = fmaf(hk, wp[64], l2);
        }
        g_LG[L * 96 + lane]      = l0;
        g_LG[L * 96 + 32 + lane] = l1;
        g_LG[L * 96 + 64 + lane] = l2;
    }
}

// ---------------- readout: lane-contiguous columns + f32x2 ------------------
__global__ void __launch_bounds__(128)
k_readout(const float* __restrict__ D1, const float* __restrict__ b1,
          const float* __restrict__ D2, const float* __restrict__ b2,
          const float* __restrict__ Wf, const float* __restrict__ bf,
          float* __restrict__ out) {
    __shared__ float sx1[4 * 8 * 256];   // per-warp [path][k] hidden1
    const int tid = threadIdx.x;
    const int lane = tid & 31, warp = tid >> 5;
    const int pbase = blockIdx.x * 32 + warp * 8;   // 100000 % 32 == 0
    float* myx1 = sx1 + warp * 2048;
    const int cb = 8 * lane;             // this lane's contiguous column base

    u64 bb1[4], bb2[4];
    ldg_v2(b1 + cb, bb1[0], bb1[1]);  ldg_v2(b1 + cb + 4, bb1[2], bb1[3]);
    ldg_v2(b2 + cb, bb2[0], bb2[1]);  ldg_v2(b2 + cb + 4, bb2[2], bb2[3]);

    float hsave[8];

    // ---- layer 1: 32 -> 256 + selu ----
    #pragma unroll 1
    for (int p = 0; p < 8; p++) {
        float hown = g_path_state[(pbase + p) * 32 + lane];
        hsave[p] = hown;
        u64 acc[4];
        #pragma unroll
        for (int i = 0; i < 4; i++) acc[i] = bb1[i];
        #pragma unroll 1
        for (int k = 0; k < 32; k++) {
            float hk = __shfl_sync(0xffffffffu, hown, k);
            u64 h2 = splat2(hk);
            const float* d1 = D1 + k * 256 + cb;
            u64 w0, w1, w2, w3;
            ldg_v2(d1, w0, w1); ldg_v2(d1 + 4, w2, w3);
            ffma2(acc[0], h2, w0); ffma2(acc[1], h2, w1);
            ffma2(acc[2], h2, w2); ffma2(acc[3], h2, w3);
        }
        float2* dst = reinterpret_cast<float2*>(myx1 + p * 256 + cb);
        #pragma unroll
        for (int i = 0; i < 4; i++) {
            float x0, x1; unpack2(acc[i], x0, x1);
            dst[i] = make_float2(seluf_(x0), seluf_(x1));
        }
    }
    __syncwarp();

    // ---- layer 2: 256 -> 256, f32x2, D2-row reuse across 8 paths ----
    u64 a2p[32];
    #pragma unroll
    for (int p = 0; p < 8; p++)
        #pragma unroll
        for (int i = 0; i < 4; i++) a2p[p * 4 + i] = bb2[i];

    #pragma unroll 1
    for (int k = 0; k < 256; k++) {
        const float* d2 = D2 + k * 256 + cb;
        u64 w0, w1, w2, w3;
        ldg_v2(d2, w0, w1); ldg_v2(d2 + 4, w2, w3);
        #pragma unroll
        for (int p = 0; p < 8; p++) {
            u64 x2 = splat2(myx1[p * 256 + k]);
            ffma2(a2p[p*4+0], x2, w0); ffma2(a2p[p*4+1], x2, w1);
            ffma2(a2p[p*4+2], x2, w2); ffma2(a2p[p*4+3], x2, w3);
        }
    }

    // ---- selu + final dense on concat(x2, h) ----
    const float2* Wf2 = reinterpret_cast<const float2*>(Wf);
    float2 wfx[8];
    #pragma unroll
    for (int i = 0; i < 8; i++) wfx[i] = __ldg(Wf2 + cb + i);
    float2 wfh = __ldg(Wf2 + 256 + lane);
    float bf0 = __ldg(bf), bf1 = __ldg(bf + 1);

    #pragma unroll 1
    for (int p = 0; p < 8; p++) {
        float hv = hsave[p];
        float s0 = hv * wfh.x, s1 = hv * wfh.y;
        #pragma unroll
        for (int i = 0; i < 4; i++) {
            float x0, x1; unpack2(a2p[p * 4 + i], x0, x1);
            x0 = seluf_(x0); x1 = seluf_(x1);
            s0 = fmaf(x0, wfx[2*i].x, fmaf(x1, wfx[2*i+1].x, s0));
            s1 = fmaf(x0, wfx[2*i].y, fmaf(x1, wfx[2*i+1].y, s1));
        }
        #pragma unroll
        for (int off = 16; off; off >>= 1) {
            s0 += __shfl_xor_sync(0xffffffffu, s0, off);
            s1 += __shfl_xor_sync(0xffffffffu, s1, off);
        }
        if (lane == 0)
            reinterpret_cast<float2*>(out)[pbase + p] = make_float2(s0 + bf0, s1 + bf1);
    }
}

// ---------------- launch ----------------
extern "C" void kernel_launch(void* const* d_in, const int* in_sizes, int n_in,
                              void* d_out, int out_size) {
    const float* cap     = (const float*)d_in[0];
    const float* traffic = (const float*)d_in[1];
    const int*   links   = (const int*)  d_in[2];
    const float* Wp = (const float*)d_in[5];
    const float* Up = (const float*)d_in[6];
    const float* bp = (const float*)d_in[7];
    const float* Wl = (const float*)d_in[8];
    const float* Ul = (const float*)d_in[9];
    const float* bl = (const float*)d_in[10];
    const float* D1 = (const float*)d_in[11];
    const float* b1 = (const float*)d_in[12];
    const float* D2 = (const float*)d_in[13];
    const float* b2 = (const float*)d_in[14];
    const float* Wf = (const float*)d_in[15];
    const float* bf = (const float*)d_in[16];
    float* out = (float*)d_out;

    k_init<<<(NPATHS * 32 + 255) / 256, 256>>>(cap, traffic, Wp, bp);
    for (int t = 0; t < 8; t++) {
        k_path<<<(NPATHS + 63) / 64, 128>>>(links, Up, bp);
        k_link<<<64, 256>>>(Wl, Ul, bl, Wp, bp);
    }
    k_readout<<<NPATHS / 32, 128>>>(D1, b1, D2, b2, Wf, bf, out);
}

// round 8
// speedup vs baseline: 1.1735x; 1.1735x over previous
#include <cuda_runtime.h>

#define NPATHS 100000
#define NLINKS 10000

// ---------------- persistent device state ----------------
__device__ __align__(16) float g_link_state[NLINKS * 32];
__device__ __align__(16) float g_path_state[NPATHS * 32];
__device__ __align__(16) float g_m[NLINKS * 32];          // segment sums
__device__ __align__(16) float g_LG[NLINKS * 96];         // link_state @ Wp + biases

// ---------------- packed f32x2 helpers ----------------
typedef unsigned long long u64;

__device__ __forceinline__ u64 splat2(float x) {
    u64 r; asm("mov.b64 %0, {%1, %1};" : "=l"(r) : "f"(x)); return r;
}
__device__ __forceinline__ u64 pack2(float a, float b) {
    u64 r; asm("mov.b64 %0, {%1, %2};" : "=l"(r) : "f"(a), "f"(b)); return r;
}
__device__ __forceinline__ void unpack2(u64 v, float& a, float& b) {
    asm("mov.b64 {%0, %1}, %2;" : "=f"(a), "=f"(b) : "l"(v));
}
__device__ __forceinline__ void ffma2(u64& d, u64 a, u64 b) {
    asm("fma.rn.f32x2 %0, %1, %2, %0;" : "+l"(d) : "l"(a), "l"(b));
}
__device__ __forceinline__ u64 lds_b64(unsigned addr) {
    u64 r; asm volatile("ld.shared.b64 %0, [%1];" : "=l"(r) : "r"(addr)); return r;
}
__device__ __forceinline__ void ldg_v2(const void* p, u64& a, u64& b) {
    asm volatile("ld.global.nc.v2.u64 {%0, %1}, [%2];" : "=l"(a), "=l"(b) : "l"(p));
}

// ---------------- fast activations ----------------
__device__ __forceinline__ float tanh_ap(float x) {
    float r; asm("tanh.approx.f32 %0, %1;" : "=f"(r) : "f"(x)); return r;
}
__device__ __forceinline__ float sigmoid_t(float x) {
    return fmaf(tanh_ap(0.5f * x), 0.5f, 0.5f);
}
__device__ __forceinline__ float seluf_(float x) {
    const float sc = 1.0507009873554805f;
    const float al = 1.6732632423543772f;
    return x > 0.0f ? sc * x : sc * al * (__expf(x) - 1.0f);
}

// ---------------- init: states, m=0, initial LG ----------------
__global__ void k_init(const float* __restrict__ cap, const float* __restrict__ traffic,
                       const float* __restrict__ Wp, const float* __restrict__ bp) {
    int idx = blockIdx.x * blockDim.x + threadIdx.x;
    if (idx < NPATHS * 32)
        g_path_state[idx] = ((idx & 31) == 0) ? traffic[idx >> 5] : 0.0f;
    if (idx < NLINKS * 32) {
        g_link_state[idx] = ((idx & 31) == 0) ? cap[idx >> 5] : 0.0f;
        g_m[idx] = 0.0f;
    }
    if (idx < NLINKS * 96) {
        int l = idx / 96;
        int j = idx - l * 96;
        float v = cap[l] * Wp[j] + bp[j];        // input bias bp[0]
        if (j < 64) v += bp[96 + j];             // fold recurrent bias bp[1] for z,r
        g_LG[idx] = v;
    }
}

// ---------------- path phase v5: lane=dim, warp=16 paths --------------------
// load-early/add-late gather, pre-splatted u64 weights, tanh.approx gates.
#define PPW 16          // paths per warp
#define NPAIR 8         // path pairs per warp
#define HSTR 9          // u64 stride per dim row (8 pairs + 1 pad)

__global__ void __launch_bounds__(128)
k_path(const int* __restrict__ links, const float* __restrict__ Up,
       const float* __restrict__ bp) {
    __shared__ __align__(16) u64 sUp2[3072];           // Up [k][j], both halves = Up[k][j]
    __shared__ int slinks[64 * 8];                     // 64 paths per block
    __shared__ __align__(16) u64 sh2[4 * 32 * HSTR];   // per warp: h[dim][pair]

    const int tid  = threadIdx.x;
    const int lane = tid & 31;
    const int warp = tid >> 5;
    const int p0   = blockIdx.x * 64;                  // 64 paths per block

    for (int i = tid; i < 3072; i += 128) sUp2[i] = splat2(Up[i]);
    for (int i = tid; i < 512; i += 128) {
        int e = p0 * 8 + i;
        slinks[i] = (e < NPATHS * 8) ? links[e] : 0;
    }
    __syncthreads();

    const int pw = p0 + warp * PPW;
    if (pw >= NPATHS) return;                          // whole-warp exit

    u64* shw = sh2 + warp * 32 * HSTR;
    float* shf = reinterpret_cast<float*>(shw);

    // load h tile: float idx = dim*2*HSTR + pathInWarp
    #pragma unroll 1
    for (int i = 0; i < PPW; i++)
        shf[lane * 2 * HSTR + i] = g_path_state[(pw + i) * 32 + lane];
    __syncwarp();

    const u64 b1h2 = splat2(__ldg(bp + 96 + 64 + lane));
    const unsigned shw_a = (unsigned)__cvta_generic_to_shared(shw);
    const unsigned sUp_a = (unsigned)__cvta_generic_to_shared(sUp2) + lane * 8;
    const int* slk = slinks + warp * PPW * 8;

    #pragma unroll 1
    for (int s = 0; s < 8; s++) {
        // prologue: issue ALL LG gather loads now; consumed only after k-loop
        float pz[PPW], pr[PPW], ph[PPW];
        #pragma unroll
        for (int q = 0; q < PPW; q++) {
            const float* lg = g_LG + slk[q * 8 + s] * 96 + lane;
            pz[q] = __ldg(lg);
            pr[q] = __ldg(lg + 32);
            ph[q] = __ldg(lg + 64);
        }

        u64 accz[NPAIR], accr[NPAIR], acch[NPAIR];
        #pragma unroll
        for (int p2 = 0; p2 < NPAIR; p2++) {
            accz[p2] = 0ull;
            accr[p2] = 0ull;
            acch[p2] = b1h2;
        }

        // recurrent matvec: acc += h @ Up (gather latency hidden underneath)
        #pragma unroll 2
        for (int k = 0; k < 32; k++) {
            unsigned wa = sUp_a + (unsigned)(k * 768);
            u64 wz2 = lds_b64(wa);
            u64 wr2 = lds_b64(wa + 256);
            u64 wh2 = lds_b64(wa + 512);
            unsigned ha = shw_a + (unsigned)(k * HSTR * 8);
            #pragma unroll
            for (int p2 = 0; p2 < NPAIR; p2++) {
                u64 h2 = lds_b64(ha + p2 * 8);
                ffma2(accz[p2], h2, wz2);
                ffma2(accr[p2], h2, wr2);
                ffma2(acch[p2], h2, wh2);
            }
        }

        // epilogue: add prefetched LG, gates, state update, coalesced scatter
        #pragma unroll
        for (int p2 = 0; p2 < NPAIR; p2++) {
            int qA = 2 * p2, qB = qA + 1;
            int lkA = slk[qA * 8 + s];
            int lkB = slk[qB * 8 + s];
            float azA, azB, arA, arB, ahA, ahB;
            unpack2(accz[p2], azA, azB);
            unpack2(accr[p2], arA, arB);
            unpack2(acch[p2], ahA, ahB);
            float* hp = shf + lane * 2 * HSTR + 2 * p2;

            float zA = sigmoid_t(azA + pz[qA]);
            float rA = sigmoid_t(arA + pr[qA]);
            float cA = tanh_ap(ph[qA] + rA * ahA);
            float hoA = hp[0];
            float hnA = cA + zA * (hoA - cA);
            hp[0] = hnA;
            atomicAdd(g_m + lkA * 32 + lane, hnA);

            float zB = sigmoid_t(azB + pz[qB]);
            float rB = sigmoid_t(arB + pr[qB]);
            float cB = tanh_ap(ph[qB] + rB * ahB);
            float hoB = hp[1];
            float hnB = cB + zB * (hoB - cB);
            hp[1] = hnB;
            atomicAdd(g_m + lkB * 32 + lane, hnB);
        }
        __syncwarp();
    }

    // writeback h tile (coalesced per path)
    #pragma unroll 1
    for (int i = 0; i < PPW; i++)
        g_path_state[(pw + i) * 32 + lane] = shf[lane * 2 * HSTR + i];
}

// ---------------- link phase (R6 form): warp per link, lane=dim -------------
__global__ void __launch_bounds__(256)
k_link(const float* __restrict__ Wl, const float* __restrict__ Ul,
       const float* __restrict__ bl, const float* __restrict__ Wp,
       const float* __restrict__ bp) {
    __shared__ float sWl[3072], sUl[3072], sWp[3072];
    __shared__ float sbl[192], sbp[192];
    const int tid = threadIdx.x;
    for (int i = tid; i < 3072; i += 256) { sWl[i] = Wl[i]; sUl[i] = Ul[i]; sWp[i] = Wp[i]; }
    if (tid < 192) { sbl[tid] = bl[tid]; sbp[tid] = bp[tid]; }
    __syncthreads();

    const int lane = tid & 31;
    const int L = blockIdx.x * 8 + (tid >> 5);        // 1250 * 8 = 10000 exact

    float mown = g_m[L * 32 + lane];
    float hown = g_link_state[L * 32 + lane];

    float az  = sbl[lane]      + sbl[96 + lane];
    float arx = sbl[32 + lane] + sbl[128 + lane];
    float axh = sbl[64 + lane];
    float ahh = sbl[160 + lane];

    #pragma unroll 1
    for (int k = 0; k < 32; k++) {
        float mk = __shfl_sync(0xffffffffu, mown, k);
        float hk = __shfl_sync(0xffffffffu, hown, k);
        const float* wl = sWl + k * 96 + lane;
        const float* ul = sUl + k * 96 + lane;
        az  = fmaf(mk, wl[0],  fmaf(hk, ul[0],  az));
        arx = fmaf(mk, wl[32], fmaf(hk, ul[32], arx));
        axh = fmaf(mk, wl[64], axh);
        ahh = fmaf(hk, ul[64], ahh);
    }

    float z  = sigmoid_t(az);
    float r  = sigmoid_t(arx);
    float c  = tanh_ap(axh + r * ahh);
    float hn = c + z * (hown - c);

    g_link_state[L * 32 + lane] = hn;
    g_m[L * 32 + lane] = 0.0f;                        // reset for next iteration

    // recompute LG = new_link_state @ Wp + biases (lane owns cols j, 32+j, 64+j)
    float l0 = sbp[lane]      + sbp[96 + lane];
    float l1 = sbp[32 + lane] + sbp[128 + lane];
    float l2 = sbp[64 + lane];
    #pragma unroll 1
    for (int k = 0; k < 32; k++) {
        float hk = __shfl_sync(0xffffffffu, hn, k);
        const float* wp = sWp + k * 96 + lane;
        l0 = fmaf(hk, wp[0],  l0);
        l1 = fmaf(hk, wp[32], l1);
        l2 = fmaf(hk, wp[64], l2);
    }
    g_LG[L * 96 + lane]      = l0;
    g_LG[L * 96 + 32 + lane] = l1;
    g_LG[L * 96 + 64 + lane] = l2;
}

// ---------------- readout: lane-contiguous columns + f32x2 ------------------
__global__ void __launch_bounds__(128)
k_readout(const float* __restrict__ D1, const float* __restrict__ b1,
          const float* __restrict__ D2, const float* __restrict__ b2,
          const float* __restrict__ Wf, const float* __restrict__ bf,
          float* __restrict__ out) {
    __shared__ float sx1[4 * 8 * 256];   // per-warp [path][k] hidden1
    const int tid = threadIdx.x;
    const int lane = tid & 31, warp = tid >> 5;
    const int pbase = blockIdx.x * 32 + warp * 8;   // 100000 % 32 == 0
    float* myx1 = sx1 + warp * 2048;
    const int cb = 8 * lane;             // this lane's contiguous column base

    u64 bb1[4], bb2[4];
    ldg_v2(b1 + cb, bb1[0], bb1[1]);  ldg_v2(b1 + cb + 4, bb1[2], bb1[3]);
    ldg_v2(b2 + cb, bb2[0], bb2[1]);  ldg_v2(b2 + cb + 4, bb2[2], bb2[3]);

    float hsave[8];

    // ---- layer 1: 32 -> 256 + selu ----
    #pragma unroll 1
    for (int p = 0; p < 8; p++) {
        float hown = g_path_state[(pbase + p) * 32 + lane];
        hsave[p] = hown;
        u64 acc[4];
        #pragma unroll
        for (int i = 0; i < 4; i++) acc[i] = bb1[i];
        #pragma unroll 1
        for (int k = 0; k < 32; k++) {
            float hk = __shfl_sync(0xffffffffu, hown, k);
            u64 h2 = splat2(hk);
            const float* d1 = D1 + k * 256 + cb;
            u64 w0, w1, w2, w3;
            ldg_v2(d1, w0, w1); ldg_v2(d1 + 4, w2, w3);
            ffma2(acc[0], h2, w0); ffma2(acc[1], h2, w1);
            ffma2(acc[2], h2, w2); ffma2(acc[3], h2, w3);
        }
        float2* dst = reinterpret_cast<float2*>(myx1 + p * 256 + cb);
        #pragma unroll
        for (int i = 0; i < 4; i++) {
            float x0, x1; unpack2(acc[i], x0, x1);
            dst[i] = make_float2(seluf_(x0), seluf_(x1));
        }
    }
    __syncwarp();

    // ---- layer 2: 256 -> 256, f32x2, D2-row reuse across 8 paths ----
    u64 a2p[32];
    #pragma unroll
    for (int p = 0; p < 8; p++)
        #pragma unroll
        for (int i = 0; i < 4; i++) a2p[p * 4 + i] = bb2[i];

    #pragma unroll 1
    for (int k = 0; k < 256; k++) {
        const float* d2 = D2 + k * 256 + cb;
        u64 w0, w1, w2, w3;
        ldg_v2(d2, w0, w1); ldg_v2(d2 + 4, w2, w3);
        #pragma unroll
        for (int p = 0; p < 8; p++) {
            u64 x2 = splat2(myx1[p * 256 + k]);
            ffma2(a2p[p*4+0], x2, w0); ffma2(a2p[p*4+1], x2, w1);
            ffma2(a2p[p*4+2], x2, w2); ffma2(a2p[p*4+3], x2, w3);
        }
    }

    // ---- selu + final dense on concat(x2, h) ----
    const float2* Wf2 = reinterpret_cast<const float2*>(Wf);
    float2 wfx[8];
    #pragma unroll
    for (int i = 0; i < 8; i++) wfx[i] = __ldg(Wf2 + cb + i);
    float2 wfh = __ldg(Wf2 + 256 + lane);
    float bf0 = __ldg(bf), bf1 = __ldg(bf + 1);

    #pragma unroll 1
    for (int p = 0; p < 8; p++) {
        float hv = hsave[p];
        float s0 = hv * wfh.x, s1 = hv * wfh.y;
        #pragma unroll
        for (int i = 0; i < 4; i++) {
            float x0, x1; unpack2(a2p[p * 4 + i], x0, x1);
            x0 = seluf_(x0); x1 = seluf_(x1);
            s0 = fmaf(x0, wfx[2*i].x, fmaf(x1, wfx[2*i+1].x, s0));
            s1 = fmaf(x0, wfx[2*i].y, fmaf(x1, wfx[2*i+1].y, s1));
        }
        #pragma unroll
        for (int off = 16; off; off >>= 1) {
            s0 += __shfl_xor_sync(0xffffffffu, s0, off);
            s1 += __shfl_xor_sync(0xffffffffu, s1, off);
        }
        if (lane == 0)
            reinterpret_cast<float2*>(out)[pbase + p] = make_float2(s0 + bf0, s1 + bf1);
    }
}

// ---------------- launch ----------------
extern "C" void kernel_launch(void* const* d_in, const int* in_sizes, int n_in,
                              void* d_out, int out_size) {
    const float* cap     = (const float*)d_in[0];
    const float* traffic = (const float*)d_in[1];
    const int*   links   = (const int*)  d_in[2];
    const float* Wp = (const float*)d_in[5];
    const float* Up = (const float*)d_in[6];
    const float* bp = (const float*)d_in[7];
    const float* Wl = (const float*)d_in[8];
    const float* Ul = (const float*)d_in[9];
    const float* bl = (const float*)d_in[10];
    const float* D1 = (const float*)d_in[11];
    const float* b1 = (const float*)d_in[12];
    const float* D2 = (const float*)d_in[13];
    const float* b2 = (const float*)d_in[14];
    const float* Wf = (const float*)d_in[15];
    const float* bf = (const float*)d_in[16];
    float* out = (float*)d_out;

    k_init<<<(NPATHS * 32 + 255) / 256, 256>>>(cap, traffic, Wp, bp);
    for (int t = 0; t < 8; t++) {
        k_path<<<(NPATHS + 63) / 64, 128>>>(links, Up, bp);
        k_link<<<NLINKS / 8, 256>>>(Wl, Ul, bl, Wp, bp);
    }
    k_readout<<<NPATHS / 32, 128>>>(D1, b1, D2, b2, Wf, bf, out);
}

// round 9
// speedup vs baseline: 1.2013x; 1.0237x over previous
#include <cuda_runtime.h>

#define NPATHS 100000
#define NLINKS 10000

// ---------------- persistent device state ----------------
__device__ __align__(16) float g_link_state[NLINKS * 32];
__device__ __align__(16) float g_path_state[NPATHS * 32];
__device__ __align__(16) float g_m[NLINKS * 32];          // segment sums
__device__ __align__(16) float g_LG[NLINKS * 96];         // link_state @ Wp + biases

// ---------------- packed f32x2 helpers ----------------
typedef unsigned long long u64;

__device__ __forceinline__ u64 splat2(float x) {
    u64 r; asm("mov.b64 %0, {%1, %1};" : "=l"(r) : "f"(x)); return r;
}
__device__ __forceinline__ u64 pack2(float a, float b) {
    u64 r; asm("mov.b64 %0, {%1, %2};" : "=l"(r) : "f"(a), "f"(b)); return r;
}
__device__ __forceinline__ void unpack2(u64 v, float& a, float& b) {
    asm("mov.b64 {%0, %1}, %2;" : "=f"(a), "=f"(b) : "l"(v));
}
__device__ __forceinline__ void ffma2(u64& d, u64 a, u64 b) {
    asm("fma.rn.f32x2 %0, %1, %2, %0;" : "+l"(d) : "l"(a), "l"(b));
}
__device__ __forceinline__ void lds_v2(unsigned addr, u64& a, u64& b) {
    asm volatile("ld.shared.v2.u64 {%0, %1}, [%2];" : "=l"(a), "=l"(b) : "r"(addr));
}
__device__ __forceinline__ void sts_v2(unsigned addr, u64 a, u64 b) {
    asm volatile("st.shared.v2.u64 [%0], {%1, %2};" :: "r"(addr), "l"(a), "l"(b) : "memory");
}
__device__ __forceinline__ void ldg_v2(const void* p, u64& a, u64& b) {
    asm volatile("ld.global.nc.v2.u64 {%0, %1}, [%2];" : "=l"(a), "=l"(b) : "l"(p));
}

// ---------------- fast activations ----------------
__device__ __forceinline__ float tanh_ap(float x) {
    float r; asm("tanh.approx.f32 %0, %1;" : "=f"(r) : "f"(x)); return r;
}
__device__ __forceinline__ float sigmoid_t(float x) {
    return fmaf(tanh_ap(0.5f * x), 0.5f, 0.5f);
}
__device__ __forceinline__ float seluf_(float x) {
    const float sc = 1.0507009873554805f;
    const float al = 1.6732632423543772f;
    return x > 0.0f ? sc * x : sc * al * (__expf(x) - 1.0f);
}

// ---------------- init: states, m=0, initial LG ----------------
__global__ void k_init(const float* __restrict__ cap, const float* __restrict__ traffic,
                       const float* __restrict__ Wp, const float* __restrict__ bp) {
    int idx = blockIdx.x * blockDim.x + threadIdx.x;
    if (idx < NPATHS * 32)
        g_path_state[idx] = ((idx & 31) == 0) ? traffic[idx >> 5] : 0.0f;
    if (idx < NLINKS * 32) {
        g_link_state[idx] = ((idx & 31) == 0) ? cap[idx >> 5] : 0.0f;
        g_m[idx] = 0.0f;
    }
    if (idx < NLINKS * 96) {
        int l = idx / 96;
        int j = idx - l * 96;
        float v = cap[l] * Wp[j] + bp[j];        // input bias bp[0]
        if (j < 64) v += bp[96 + j];             // fold recurrent bias bp[1] for z,r
        g_LG[idx] = v;
    }
}

// ---------------- path phase v6: lane=dim, warp=16 paths --------------------
// h tile as XOR-swizzled u64 pairs (v2 loads), f32 weights + reg splat,
// load-early/add-late gather, tanh.approx gates.
#define PPW 16          // paths per warp
#define NPAIR 8         // path pairs per warp
#define HSTRB 80u       // bytes per dim row (10 u64: 4 groups x 16B + 16B pad)

__global__ void __launch_bounds__(128)
k_path(const int* __restrict__ links, const float* __restrict__ Up,
       const float* __restrict__ bp) {
    __shared__ __align__(16) float sUp[3072];            // Up [k][j] row-major f32
    __shared__ int slinks[64 * 8];                       // 64 paths per block
    __shared__ __align__(16) char shtile[4 * 32 * HSTRB];// per warp: h[dim][group swz]

    const int tid  = threadIdx.x;
    const int lane = tid & 31;
    const int warp = tid >> 5;
    const int p0   = blockIdx.x * 64;                    // 64 paths per block

    for (int i = tid; i < 3072; i += 128) sUp[i] = Up[i];
    for (int i = tid; i < 512; i += 128) {
        int e = p0 * 8 + i;
        slinks[i] = (e < NPATHS * 8) ? links[e] : 0;
    }
    __syncthreads();

    const int pw = p0 + warp * PPW;
    if (pw >= NPATHS) return;                            // whole-warp exit

    char* shw = shtile + warp * 32 * HSTRB;
    float* shwf = reinterpret_cast<float*>(shw);
    const unsigned shw_a = (unsigned)__cvta_generic_to_shared(shw);
    const unsigned sl16 = ((unsigned)(lane >> 3) & 3u) * 16u;   // owner-dim swizzle (bytes)

    // initial h load: float slot = lane*20 + (((i>>2)*4) ^ (sl16>>2)) + (i&3)
    #pragma unroll 1
    for (int i = 0; i < PPW; i++)
        shwf[lane * 20 + ((((unsigned)i >> 2) * 4u) ^ (sl16 >> 2)) + (i & 3)] =
            g_path_state[(pw + i) * 32 + lane];
    __syncwarp();

    const u64 b1h2 = splat2(__ldg(bp + 96 + 64 + lane));
    const int* slk = slinks + warp * PPW * 8;

    #pragma unroll 1
    for (int s = 0; s < 8; s++) {
        // prologue: issue ALL LG gather loads now; consumed only after k-loop
        float pz[PPW], pr[PPW], ph[PPW];
        #pragma unroll
        for (int q = 0; q < PPW; q++) {
            const float* lg = g_LG + slk[q * 8 + s] * 96 + lane;
            pz[q] = __ldg(lg);
            pr[q] = __ldg(lg + 32);
            ph[q] = __ldg(lg + 64);
        }

        u64 accz[NPAIR], accr[NPAIR], acch[NPAIR];
        #pragma unroll
        for (int p2 = 0; p2 < NPAIR; p2++) {
            accz[p2] = 0ull;
            accr[p2] = 0ull;
            acch[p2] = b1h2;
        }

        // recurrent matvec: acc += h @ Up (gather latency hidden underneath)
        #pragma unroll 2
        for (int k = 0; k < 32; k++) {
            const float* w = sUp + k * 96 + lane;
            u64 wz2 = splat2(w[0]);
            u64 wr2 = splat2(w[32]);
            u64 wh2 = splat2(w[64]);
            unsigned ha = shw_a + (unsigned)k * HSTRB;
            unsigned sk16 = ((unsigned)(k >> 3) & 3u) * 16u;
            #pragma unroll
            for (int g = 0; g < 4; g++) {
                u64 hA, hB;
                lds_v2(ha + (((unsigned)g * 16u) ^ sk16), hA, hB);
                ffma2(accz[2*g],   hA, wz2);
                ffma2(accz[2*g+1], hB, wz2);
                ffma2(accr[2*g],   hA, wr2);
                ffma2(accr[2*g+1], hB, wr2);
                ffma2(acch[2*g],   hA, wh2);
                ffma2(acch[2*g+1], hB, wh2);
            }
        }

        // epilogue: add prefetched LG, gates, state update, coalesced scatter
        #pragma unroll
        for (int g = 0; g < 4; g++) {
            const int q0 = 4 * g;
            unsigned ea = shw_a + (unsigned)lane * HSTRB + (((unsigned)g * 16u) ^ sl16);
            u64 hoA2, hoB2;
            lds_v2(ea, hoA2, hoB2);
            float ho0, ho1, ho2, ho3;
            unpack2(hoA2, ho0, ho1);
            unpack2(hoB2, ho2, ho3);

            float az0, az1, az2v, az3, ar0, ar1, ar2v, ar3, ah0, ah1, ah2v, ah3;
            unpack2(accz[2*g], az0, az1);   unpack2(accz[2*g+1], az2v, az3);
            unpack2(accr[2*g], ar0, ar1);   unpack2(accr[2*g+1], ar2v, ar3);
            unpack2(acch[2*g], ah0, ah1);   unpack2(acch[2*g+1], ah2v, ah3);

            float z0 = sigmoid_t(az0 + pz[q0]);
            float r0 = sigmoid_t(ar0 + pr[q0]);
            float c0 = tanh_ap(ph[q0] + r0 * ah0);
            float hn0 = c0 + z0 * (ho0 - c0);

            float z1 = sigmoid_t(az1 + pz[q0 + 1]);
            float r1 = sigmoid_t(ar1 + pr[q0 + 1]);
            float c1 = tanh_ap(ph[q0 + 1] + r1 * ah1);
            float hn1 = c1 + z1 * (ho1 - c1);

            float z2 = sigmoid_t(az2v + pz[q0 + 2]);
            float r2 = sigmoid_t(ar2v + pr[q0 + 2]);
            float c2 = tanh_ap(ph[q0 + 2] + r2 * ah2v);
            float hn2 = c2 + z2 * (ho2 - c2);

            float z3 = sigmoid_t(az3 + pz[q0 + 3]);
            float r3 = sigmoid_t(ar3 + pr[q0 + 3]);
            float c3 = tanh_ap(ph[q0 + 3] + r3 * ah3);
            float hn3 = c3 + z3 * (ho3 - c3);

            sts_v2(ea, pack2(hn0, hn1), pack2(hn2, hn3));

            atomicAdd(g_m + slk[(q0    ) * 8 + s] * 32 + lane, hn0);
            atomicAdd(g_m + slk[(q0 + 1) * 8 + s] * 32 + lane, hn1);
            atomicAdd(g_m + slk[(q0 + 2) * 8 + s] * 32 + lane, hn2);
            atomicAdd(g_m + slk[(q0 + 3) * 8 + s] * 32 + lane, hn3);
        }
        __syncwarp();
    }

    // writeback h tile (coalesced per path)
    #pragma unroll 1
    for (int i = 0; i < PPW; i++)
        g_path_state[(pw + i) * 32 + lane] =
            shwf[lane * 20 + ((((unsigned)i >> 2) * 4u) ^ (sl16 >> 2)) + (i & 3)];
}

// ---------------- link phase: warp per link, lane=dim -----------------------
__global__ void __launch_bounds__(256)
k_link(const float* __restrict__ Wl, const float* __restrict__ Ul,
       const float* __restrict__ bl, const float* __restrict__ Wp,
       const float* __restrict__ bp) {
    __shared__ float sWl[3072], sUl[3072], sWp[3072];
    __shared__ float sbl[192], sbp[192];
    const int tid = threadIdx.x;
    for (int i = tid; i < 3072; i += 256) { sWl[i] = Wl[i]; sUl[i] = Ul[i]; sWp[i] = Wp[i]; }
    if (tid < 192) { sbl[tid] = bl[tid]; sbp[tid] = bp[tid]; }
    __syncthreads();

    const int lane = tid & 31;
    const int L = blockIdx.x * 8 + (tid >> 5);        // 1250 * 8 = 10000 exact

    float mown = g_m[L * 32 + lane];
    float hown = g_link_state[L * 32 + lane];

    float az  = sbl[lane]      + sbl[96 + lane];
    float arx = sbl[32 + lane] + sbl[128 + lane];
    float axh = sbl[64 + lane];
    float ahh = sbl[160 + lane];

    #pragma unroll 1
    for (int k = 0; k < 32; k++) {
        float mk = __shfl_sync(0xffffffffu, mown, k);
        float hk = __shfl_sync(0xffffffffu, hown, k);
        const float* wl = sWl + k * 96 + lane;
        const float* ul = sUl + k * 96 + lane;
        az  = fmaf(mk, wl[0],  fmaf(hk, ul[0],  az));
        arx = fmaf(mk, wl[32], fmaf(hk, ul[32], arx));
        axh = fmaf(mk, wl[64], axh);
        ahh = fmaf(hk, ul[64], ahh);
    }

    float z  = sigmoid_t(az);
    float r  = sigmoid_t(arx);
    float c  = tanh_ap(axh + r * ahh);
    float hn = c + z * (hown - c);

    g_link_state[L * 32 + lane] = hn;
    g_m[L * 32 + lane] = 0.0f;                        // reset for next iteration

    // recompute LG = new_link_state @ Wp + biases (lane owns cols j, 32+j, 64+j)
    float l0 = sbp[lane]      + sbp[96 + lane];
    float l1 = sbp[32 + lane] + sbp[128 + lane];
    float l2 = sbp[64 + lane];
    #pragma unroll 1
    for (int k = 0; k < 32; k++) {
        float hk = __shfl_sync(0xffffffffu, hn, k);
        const float* wp = sWp + k * 96 + lane;
        l0 = fmaf(hk, wp[0],  l0);
        l1 = fmaf(hk, wp[32], l1);
        l2 = fmaf(hk, wp[64], l2);
    }
    g_LG[L * 96 + lane]      = l0;
    g_LG[L * 96 + 32 + lane] = l1;
    g_LG[L * 96 + 64 + lane] = l2;
}

// ---------------- readout: lane-contiguous columns + f32x2 ------------------
__global__ void __launch_bounds__(128)
k_readout(const float* __restrict__ D1, const float* __restrict__ b1,
          const float* __restrict__ D2, const float* __restrict__ b2,
          const float* __restrict__ Wf, const float* __restrict__ bf,
          float* __restrict__ out) {
    __shared__ float sx1[4 * 8 * 256];   // per-warp [path][k] hidden1
    const int tid = threadIdx.x;
    const int lane = tid & 31, warp = tid >> 5;
    const int pbase = blockIdx.x * 32 + warp * 8;   // 100000 % 32 == 0
    float* myx1 = sx1 + warp * 2048;
    const int cb = 8 * lane;             // this lane's contiguous column base

    u64 bb1[4], bb2[4];
    ldg_v2(b1 + cb, bb1[0], bb1[1]);  ldg_v2(b1 + cb + 4, bb1[2], bb1[3]);
    ldg_v2(b2 + cb, bb2[0], bb2[1]);  ldg_v2(b2 + cb + 4, bb2[2], bb2[3]);

    float hsave[8];

    // ---- layer 1: 32 -> 256 + selu ----
    #pragma unroll 1
    for (int p = 0; p < 8; p++) {
        float hown = g_path_state[(pbase + p) * 32 + lane];
        hsave[p] = hown;
        u64 acc[4];
        #pragma unroll
        for (int i = 0; i < 4; i++) acc[i] = bb1[i];
        #pragma unroll 1
        for (int k = 0; k < 32; k++) {
            float hk = __shfl_sync(0xffffffffu, hown, k);
            u64 h2 = splat2(hk);
            const float* d1 = D1 + k * 256 + cb;
            u64 w0, w1, w2, w3;
            ldg_v2(d1, w0, w1); ldg_v2(d1 + 4, w2, w3);
            ffma2(acc[0], h2, w0); ffma2(acc[1], h2, w1);
            ffma2(acc[2], h2, w2); ffma2(acc[3], h2, w3);
        }
        float2* dst = reinterpret_cast<float2*>(myx1 + p * 256 + cb);
        #pragma unroll
        for (int i = 0; i < 4; i++) {
            float x0, x1; unpack2(acc[i], x0, x1);
            dst[i] = make_float2(seluf_(x0), seluf_(x1));
        }
    }
    __syncwarp();

    // ---- layer 2: 256 -> 256, f32x2, D2-row reuse across 8 paths ----
    u64 a2p[32];
    #pragma unroll
    for (int p = 0; p < 8; p++)
        #pragma unroll
        for (int i = 0; i < 4; i++) a2p[p * 4 + i] = bb2[i];

    #pragma unroll 1
    for (int k = 0; k < 256; k++) {
        const float* d2 = D2 + k * 256 + cb;
        u64 w0, w1, w2, w3;
        ldg_v2(d2, w0, w1); ldg_v2(d2 + 4, w2, w3);
        #pragma unroll
        for (int p = 0; p < 8; p++) {
            u64 x2 = splat2(myx1[p * 256 + k]);
            ffma2(a2p[p*4+0], x2, w0); ffma2(a2p[p*4+1], x2, w1);
            ffma2(a2p[p*4+2], x2, w2); ffma2(a2p[p*4+3], x2, w3);
        }
    }

    // ---- selu + final dense on concat(x2, h) ----
    const float2* Wf2 = reinterpret_cast<const float2*>(Wf);
    float2 wfx[8];
    #pragma unroll
    for (int i = 0; i < 8; i++) wfx[i] = __ldg(Wf2 + cb + i);
    float2 wfh = __ldg(Wf2 + 256 + lane);
    float bf0 = __ldg(bf), bf1 = __ldg(bf + 1);

    #pragma unroll 1
    for (int p = 0; p < 8; p++) {
        float hv = hsave[p];
        float s0 = hv * wfh.x, s1 = hv * wfh.y;
        #pragma unroll
        for (int i = 0; i < 4; i++) {
            float x0, x1; unpack2(a2p[p * 4 + i], x0, x1);
            x0 = seluf_(x0); x1 = seluf_(x1);
            s0 = fmaf(x0, wfx[2*i].x, fmaf(x1, wfx[2*i+1].x, s0));
            s1 = fmaf(x0, wfx[2*i].y, fmaf(x1, wfx[2*i+1].y, s1));
        }
        #pragma unroll
        for (int off = 16; off; off >>= 1) {
            s0 += __shfl_xor_sync(0xffffffffu, s0, off);
            s1 += __shfl_xor_sync(0xffffffffu, s1, off);
        }
        if (lane == 0)
            reinterpret_cast<float2*>(out)[pbase + p] = make_float2(s0 + bf0, s1 + bf1);
    }
}

// ---------------- launch ----------------
extern "C" void kernel_launch(void* const* d_in, const int* in_sizes, int n_in,
                              void* d_out, int out_size) {
    const float* cap     = (const float*)d_in[0];
    const float* traffic = (const float*)d_in[1];
    const int*   links   = (const int*)  d_in[2];
    const float* Wp = (const float*)d_in[5];
    const float* Up = (const float*)d_in[6];
    const float* bp = (const float*)d_in[7];
    const float* Wl = (const float*)d_in[8];
    const float* Ul = (const float*)d_in[9];
    const float* bl = (const float*)d_in[10];
    const float* D1 = (const float*)d_in[11];
    const float* b1 = (const float*)d_in[12];
    const float* D2 = (const float*)d_in[13];
    const float* b2 = (const float*)d_in[14];
    const float* Wf = (const float*)d_in[15];
    const float* bf = (const float*)d_in[16];
    float* out = (float*)d_out;

    k_init<<<(NPATHS * 32 + 255) / 256, 256>>>(cap, traffic, Wp, bp);
    for (int t = 0; t < 8; t++) {
        k_path<<<(NPATHS + 63) / 64, 128>>>(links, Up, bp);
        k_link<<<NLINKS / 8, 256>>>(Wl, Ul, bl, Wp, bp);
    }
    k_readout<<<NPATHS / 32, 128>>>(D1, b1, D2, b2, Wf, bf, out);
}

// round 10
// speedup vs baseline: 1.2061x; 1.0040x over previous
#include <cuda_runtime.h>

#define NPATHS 100000
#define NLINKS 10000

// ---------------- persistent device state ----------------
__device__ __align__(16) float g_link_state[NLINKS * 32];
__device__ __align__(16) float g_path_state[NPATHS * 32];
__device__ __align__(16) float g_m[NLINKS * 32];          // segment sums
__device__ __align__(16) float g_LG[NLINKS * 96];         // link_state @ Wp + biases

// ---------------- packed f32x2 helpers ----------------
typedef unsigned long long u64;

__device__ __forceinline__ u64 splat2(float x) {
    u64 r; asm("mov.b64 %0, {%1, %1};" : "=l"(r) : "f"(x)); return r;
}
__device__ __forceinline__ u64 pack2(float a, float b) {
    u64 r; asm("mov.b64 %0, {%1, %2};" : "=l"(r) : "f"(a), "f"(b)); return r;
}
__device__ __forceinline__ void unpack2(u64 v, float& a, float& b) {
    asm("mov.b64 {%0, %1}, %2;" : "=f"(a), "=f"(b) : "l"(v));
}
__device__ __forceinline__ void ffma2(u64& d, u64 a, u64 b) {
    asm("fma.rn.f32x2 %0, %1, %2, %0;" : "+l"(d) : "l"(a), "l"(b));
}
__device__ __forceinline__ void lds_v2(unsigned addr, u64& a, u64& b) {
    asm volatile("ld.shared.v2.u64 {%0, %1}, [%2];" : "=l"(a), "=l"(b) : "r"(addr));
}
__device__ __forceinline__ void sts_v2(unsigned addr, u64 a, u64 b) {
    asm volatile("st.shared.v2.u64 [%0], {%1, %2};" :: "r"(addr), "l"(a), "l"(b) : "memory");
}
__device__ __forceinline__ void ldg_v2(const void* p, u64& a, u64& b) {
    asm volatile("ld.global.nc.v2.u64 {%0, %1}, [%2];" : "=l"(a), "=l"(b) : "l"(p));
}

// ---------------- fast activations ----------------
__device__ __forceinline__ float tanh_ap(float x) {
    float r; asm("tanh.approx.f32 %0, %1;" : "=f"(r) : "f"(x)); return r;
}
__device__ __forceinline__ float sigmoid_t(float x) {
    return fmaf(tanh_ap(0.5f * x), 0.5f, 0.5f);
}
__device__ __forceinline__ float seluf_(float x) {
    const float sc = 1.0507009873554805f;
    const float al = 1.6732632423543772f;
    return x > 0.0f ? sc * x : sc * al * (__expf(x) - 1.0f);
}

// ---------------- init: states, m=0, initial LG ----------------
__global__ void k_init(const float* __restrict__ cap, const float* __restrict__ traffic,
                       const float* __restrict__ Wp, const float* __restrict__ bp) {
    int idx = blockIdx.x * blockDim.x + threadIdx.x;
    if (idx < NPATHS * 32)
        g_path_state[idx] = ((idx & 31) == 0) ? traffic[idx >> 5] : 0.0f;
    if (idx < NLINKS * 32) {
        g_link_state[idx] = ((idx & 31) == 0) ? cap[idx >> 5] : 0.0f;
        g_m[idx] = 0.0f;
    }
    if (idx < NLINKS * 96) {
        int l = idx / 96;
        int j = idx - l * 96;
        float v = cap[l] * Wp[j] + bp[j];        // input bias bp[0]
        if (j < 64) v += bp[96 + j];             // fold recurrent bias bp[1] for z,r
        g_LG[idx] = v;
    }
}

// ---------------- path phase v7: lane=dim, warp=16 paths --------------------
// z/r gather folded into accumulator init (after batch-issuing all loads),
// ph kept prefetched; occupancy forced to 5 blocks/SM.
#define PPW 16          // paths per warp
#define NPAIR 8         // path pairs per warp
#define HSTRB 80u       // bytes per dim row (10 u64: 4 groups x 16B + 16B pad)

__global__ void __launch_bounds__(128, 5)
k_path(const int* __restrict__ links, const float* __restrict__ Up,
       const float* __restrict__ bp) {
    __shared__ __align__(16) float sUp[3072];            // Up [k][j] row-major f32
    __shared__ int slinks[64 * 8];                       // 64 paths per block
    __shared__ __align__(16) char shtile[4 * 32 * HSTRB];// per warp: h[dim][group swz]

    const int tid  = threadIdx.x;
    const int lane = tid & 31;
    const int warp = tid >> 5;
    const int p0   = blockIdx.x * 64;                    // 64 paths per block

    for (int i = tid; i < 3072; i += 128) sUp[i] = Up[i];
    for (int i = tid; i < 512; i += 128) {
        int e = p0 * 8 + i;
        slinks[i] = (e < NPATHS * 8) ? links[e] : 0;
    }
    __syncthreads();

    const int pw = p0 + warp * PPW;
    if (pw >= NPATHS) return;                            // whole-warp exit

    char* shw = shtile + warp * 32 * HSTRB;
    float* shwf = reinterpret_cast<float*>(shw);
    const unsigned shw_a = (unsigned)__cvta_generic_to_shared(shw);
    const unsigned sl16 = ((unsigned)(lane >> 3) & 3u) * 16u;   // owner-dim swizzle (bytes)

    // initial h load: float slot = lane*20 + (((i>>2)*4) ^ (sl16>>2)) + (i&3)
    #pragma unroll 1
    for (int i = 0; i < PPW; i++)
        shwf[lane * 20 + ((((unsigned)i >> 2) * 4u) ^ (sl16 >> 2)) + (i & 3)] =
            g_path_state[(pw + i) * 32 + lane];
    __syncwarp();

    const u64 b1h2 = splat2(__ldg(bp + 96 + 64 + lane));
    const int* slk = slinks + warp * PPW * 8;

    #pragma unroll 1
    for (int s = 0; s < 8; s++) {
        // prologue: issue ALL LG gather loads, then fold z/r into acc init.
        float pz[PPW], pr[PPW], ph[PPW];
        #pragma unroll
        for (int q = 0; q < PPW; q++) {
            const float* lg = g_LG + slk[q * 8 + s] * 96 + lane;
            pz[q] = __ldg(lg);
            pr[q] = __ldg(lg + 32);
            ph[q] = __ldg(lg + 64);
        }

        u64 accz[NPAIR], accr[NPAIR], acch[NPAIR];
        #pragma unroll
        for (int p2 = 0; p2 < NPAIR; p2++) {
            accz[p2] = pack2(pz[2 * p2], pz[2 * p2 + 1]);
            accr[p2] = pack2(pr[2 * p2], pr[2 * p2 + 1]);
            acch[p2] = b1h2;
        }

        // recurrent matvec: acc += h @ Up
        #pragma unroll 2
        for (int k = 0; k < 32; k++) {
            const float* w = sUp + k * 96 + lane;
            u64 wz2 = splat2(w[0]);
            u64 wr2 = splat2(w[32]);
            u64 wh2 = splat2(w[64]);
            unsigned ha = shw_a + (unsigned)k * HSTRB;
            unsigned sk16 = ((unsigned)(k >> 3) & 3u) * 16u;
            #pragma unroll
            for (int g = 0; g < 4; g++) {
                u64 hA, hB;
                lds_v2(ha + (((unsigned)g * 16u) ^ sk16), hA, hB);
                ffma2(accz[2*g],   hA, wz2);
                ffma2(accz[2*g+1], hB, wz2);
                ffma2(accr[2*g],   hA, wr2);
                ffma2(accr[2*g+1], hB, wr2);
                ffma2(acch[2*g],   hA, wh2);
                ffma2(acch[2*g+1], hB, wh2);
            }
        }

        // epilogue: gates, state update, coalesced scatter
        #pragma unroll
        for (int g = 0; g < 4; g++) {
            const int q0 = 4 * g;
            unsigned ea = shw_a + (unsigned)lane * HSTRB + (((unsigned)g * 16u) ^ sl16);
            u64 hoA2, hoB2;
            lds_v2(ea, hoA2, hoB2);
            float ho0, ho1, ho2, ho3;
            unpack2(hoA2, ho0, ho1);
            unpack2(hoB2, ho2, ho3);

            float az0, az1, az2v, az3, ar0, ar1, ar2v, ar3, ah0, ah1, ah2v, ah3;
            unpack2(accz[2*g], az0, az1);   unpack2(accz[2*g+1], az2v, az3);
            unpack2(accr[2*g], ar0, ar1);   unpack2(accr[2*g+1], ar2v, ar3);
            unpack2(acch[2*g], ah0, ah1);   unpack2(acch[2*g+1], ah2v, ah3);

            float z0 = sigmoid_t(az0);
            float r0 = sigmoid_t(ar0);
            float c0 = tanh_ap(ph[q0] + r0 * ah0);
            float hn0 = c0 + z0 * (ho0 - c0);

            float z1 = sigmoid_t(az1);
            float r1 = sigmoid_t(ar1);
            float c1 = tanh_ap(ph[q0 + 1] + r1 * ah1);
            float hn1 = c1 + z1 * (ho1 - c1);

            float z2 = sigmoid_t(az2v);
            float r2 = sigmoid_t(ar2v);
            float c2 = tanh_ap(ph[q0 + 2] + r2 * ah2v);
            float hn2 = c2 + z2 * (ho2 - c2);

            float z3 = sigmoid_t(az3);
            float r3 = sigmoid_t(ar3);
            float c3 = tanh_ap(ph[q0 + 3] + r3 * ah3);
            float hn3 = c3 + z3 * (ho3 - c3);

            sts_v2(ea, pack2(hn0, hn1), pack2(hn2, hn3));

            atomicAdd(g_m + slk[(q0    ) * 8 + s] * 32 + lane, hn0);
            atomicAdd(g_m + slk[(q0 + 1) * 8 + s] * 32 + lane, hn1);
            atomicAdd(g_m + slk[(q0 + 2) * 8 + s] * 32 + lane, hn2);
            atomicAdd(g_m + slk[(q0 + 3) * 8 + s] * 32 + lane, hn3);
        }
        __syncwarp();
    }

    // writeback h tile (coalesced per path)
    #pragma unroll 1
    for (int i = 0; i < PPW; i++)
        g_path_state[(pw + i) * 32 + lane] =
            shwf[lane * 20 + ((((unsigned)i >> 2) * 4u) ^ (sl16 >> 2)) + (i & 3)];
}

// ---------------- link phase: warp per link, 1024-thread blocks -------------
__global__ void __launch_bounds__(1024)
k_link(const float* __restrict__ Wl, const float* __restrict__ Ul,
       const float* __restrict__ bl, const float* __restrict__ Wp,
       const float* __restrict__ bp) {
    __shared__ float sWl[3072], sUl[3072], sWp[3072];
    __shared__ float sbl[192], sbp[192];
    const int tid = threadIdx.x;
    for (int i = tid; i < 3072; i += 1024) { sWl[i] = Wl[i]; sUl[i] = Ul[i]; sWp[i] = Wp[i]; }
    if (tid < 192) { sbl[tid] = bl[tid]; sbp[tid] = bp[tid]; }
    __syncthreads();

    const int lane = tid & 31;
    const int L = blockIdx.x * 32 + (tid >> 5);       // 313 blocks x 32 warps
    if (L >= NLINKS) return;

    float mown = g_m[L * 32 + lane];
    float hown = g_link_state[L * 32 + lane];

    float az  = sbl[lane]      + sbl[96 + lane];
    float arx = sbl[32 + lane] + sbl[128 + lane];
    float axh = sbl[64 + lane];
    float ahh = sbl[160 + lane];

    #pragma unroll 1
    for (int k = 0; k < 32; k++) {
        float mk = __shfl_sync(0xffffffffu, mown, k);
        float hk = __shfl_sync(0xffffffffu, hown, k);
        const float* wl = sWl + k * 96 + lane;
        const float* ul = sUl + k * 96 + lane;
        az  = fmaf(mk, wl[0],  fmaf(hk, ul[0],  az));
        arx = fmaf(mk, wl[32], fmaf(hk, ul[32], arx));
        axh = fmaf(mk, wl[64], axh);
        ahh = fmaf(hk, ul[64], ahh);
    }

    float z  = sigmoid_t(az);
    float r  = sigmoid_t(arx);
    float c  = tanh_ap(axh + r * ahh);
    float hn = c + z * (hown - c);

    g_link_state[L * 32 + lane] = hn;
    g_m[L * 32 + lane] = 0.0f;                        // reset for next iteration

    // recompute LG = new_link_state @ Wp + biases (lane owns cols j, 32+j, 64+j)
    float l0 = sbp[lane]      + sbp[96 + lane];
    float l1 = sbp[32 + lane] + sbp[128 + lane];
    float l2 = sbp[64 + lane];
    #pragma unroll 1
    for (int k = 0; k < 32; k++) {
        float hk = __shfl_sync(0xffffffffu, hn, k);
        const float* wp = sWp + k * 96 + lane;
        l0 = fmaf(hk, wp[0],  l0);
        l1 = fmaf(hk, wp[32], l1);
        l2 = fmaf(hk, wp[64], l2);
    }
    g_LG[L * 96 + lane]      = l0;
    g_LG[L * 96 + 32 + lane] = l1;
    g_LG[L * 96 + 64 + lane] = l2;
}

// ---------------- readout: lane-contiguous columns + f32x2 ------------------
__global__ void __launch_bounds__(128)
k_readout(const float* __restrict__ D1, const float* __restrict__ b1,
          const float* __restrict__ D2, const float* __restrict__ b2,
          const float* __restrict__ Wf, const float* __restrict__ bf,
          float* __restrict__ out) {
    __shared__ float sx1[4 * 8 * 256];   // per-warp [path][k] hidden1
    const int tid = threadIdx.x;
    const int lane = tid & 31, warp = tid >> 5;
    const int pbase = blockIdx.x * 32 + warp * 8;   // 100000 % 32 == 0
    float* myx1 = sx1 + warp * 2048;
    const int cb = 8 * lane;             // this lane's contiguous column base

    u64 bb1[4], bb2[4];
    ldg_v2(b1 + cb, bb1[0], bb1[1]);  ldg_v2(b1 + cb + 4, bb1[2], bb1[3]);
    ldg_v2(b2 + cb, bb2[0], bb2[1]);  ldg_v2(b2 + cb + 4, bb2[2], bb2[3]);

    float hsave[8];

    // ---- layer 1: 32 -> 256 + selu ----
    #pragma unroll 1
    for (int p = 0; p < 8; p++) {
        float hown = g_path_state[(pbase + p) * 32 + lane];
        hsave[p] = hown;
        u64 acc[4];
        #pragma unroll
        for (int i = 0; i < 4; i++) acc[i] = bb1[i];
        #pragma unroll 1
        for (int k = 0; k < 32; k++) {
            float hk = __shfl_sync(0xffffffffu, hown, k);
            u64 h2 = splat2(hk);
            const float* d1 = D1 + k * 256 + cb;
            u64 w0, w1, w2, w3;
            ldg_v2(d1, w0, w1); ldg_v2(d1 + 4, w2, w3);
            ffma2(acc[0], h2, w0); ffma2(acc[1], h2, w1);
            ffma2(acc[2], h2, w2); ffma2(acc[3], h2, w3);
        }
        float2* dst = reinterpret_cast<float2*>(myx1 + p * 256 + cb);
        #pragma unroll
        for (int i = 0; i < 4; i++) {
            float x0, x1; unpack2(acc[i], x0, x1);
            dst[i] = make_float2(seluf_(x0), seluf_(x1));
        }
    }
    __syncwarp();

    // ---- layer 2: 256 -> 256, f32x2, D2-row reuse across 8 paths ----
    u64 a2p[32];
    #pragma unroll
    for (int p = 0; p < 8; p++)
        #pragma unroll
        for (int i = 0; i < 4; i++) a2p[p * 4 + i] = bb2[i];

    #pragma unroll 1
    for (int k = 0; k < 256; k++) {
        const float* d2 = D2 + k * 256 + cb;
        u64 w0, w1, w2, w3;
        ldg_v2(d2, w0, w1); ldg_v2(d2 + 4, w2, w3);
        #pragma unroll
        for (int p = 0; p < 8; p++) {
            u64 x2 = splat2(myx1[p * 256 + k]);
            ffma2(a2p[p*4+0], x2, w0); ffma2(a2p[p*4+1], x2, w1);
            ffma2(a2p[p*4+2], x2, w2); ffma2(a2p[p*4+3], x2, w3);
        }
    }

    // ---- selu + final dense on concat(x2, h) ----
    const float2* Wf2 = reinterpret_cast<const float2*>(Wf);
    float2 wfx[8];
    #pragma unroll
    for (int i = 0; i < 8; i++) wfx[i] = __ldg(Wf2 + cb + i);
    float2 wfh = __ldg(Wf2 + 256 + lane);
    float bf0 = __ldg(bf), bf1 = __ldg(bf + 1);

    #pragma unroll 1
    for (int p = 0; p < 8; p++) {
        float hv = hsave[p];
        float s0 = hv * wfh.x, s1 = hv * wfh.y;
        #pragma unroll
        for (int i = 0; i < 4; i++) {
            float x0, x1; unpack2(a2p[p * 4 + i], x0, x1);
            x0 = seluf_(x0); x1 = seluf_(x1);
            s0 = fmaf(x0, wfx[2*i].x, fmaf(x1, wfx[2*i+1].x, s0));
            s1 = fmaf(x0, wfx[2*i].y, fmaf(x1, wfx[2*i+1].y, s1));
        }
        #pragma unroll
        for (int off = 16; off; off >>= 1) {
            s0 += __shfl_xor_sync(0xffffffffu, s0, off);
            s1 += __shfl_xor_sync(0xffffffffu, s1, off);
        }
        if (lane == 0)
            reinterpret_cast<float2*>(out)[pbase + p] = make_float2(s0 + bf0, s1 + bf1);
    }
}

// ---------------- launch ----------------
extern "C" void kernel_launch(void* const* d_in, const int* in_sizes, int n_in,
                              void* d_out, int out_size) {
    const float* cap     = (const float*)d_in[0];
    const float* traffic = (const float*)d_in[1];
    const int*   links   = (const int*)  d_in[2];
    const float* Wp = (const float*)d_in[5];
    const float* Up = (const float*)d_in[6];
    const float* bp = (const float*)d_in[7];
    const float* Wl = (const float*)d_in[8];
    const float* Ul = (const float*)d_in[9];
    const float* bl = (const float*)d_in[10];
    const float* D1 = (const float*)d_in[11];
    const float* b1 = (const float*)d_in[12];
    const float* D2 = (const float*)d_in[13];
    const float* b2 = (const float*)d_in[14];
    const float* Wf = (const float*)d_in[15];
    const float* bf = (const float*)d_in[16];
    float* out = (float*)d_out;

    k_init<<<(NPATHS * 32 + 255) / 256, 256>>>(cap, traffic, Wp, bp);
    for (int t = 0; t < 8; t++) {
        k_path<<<(NPATHS + 63) / 64, 128>>>(links, Up, bp);
        k_link<<<(NLINKS + 31) / 32, 1024>>>(Wl, Ul, bl, Wp, bp);
    }
    k_readout<<<NPATHS / 32, 128>>>(D1, b1, D2, b2, Wf, bf, out);
}